// round 4
// baseline (speedup 1.0000x reference)
#include <cuda_runtime.h>
#include <cstdint>

#define FULLMASK 0xFFFFFFFFu
#define MAXC  16
#define BMAX  4096
#define NS    128
#define KMAXC 128
#define PW    128
#define TMAIN 512

__device__ int      d_gid[BMAX];
__device__ int      d_pos[BMAX];
__device__ int      d_cn[MAXC];
__device__ int      d_ck[MAXC];
__device__ int      d_cm[MAXC];
__device__ unsigned d_key0[MAXC];
__device__ unsigned d_key1[MAXC];
__device__ int      d_gsz[MAXC];
__device__ int      d_val[MAXC];
__device__ float    d_pen[BMAX];

// TF32 round-to-nearest-even (13 low mantissa bits dropped).
__device__ __forceinline__ float tf32_rne(float x) {
  unsigned u = __float_as_uint(x);
  u = (u + 0xFFFu + ((u >> 13) & 1u)) & 0xFFFFE000u;
  return __uint_as_float(u);
}
__device__ __forceinline__ float4 tf32_rne4(float4 v) {
  v.x = tf32_rne(v.x); v.y = tf32_rne(v.y);
  v.z = tf32_rne(v.z); v.w = tf32_rne(v.w);
  return v;
}

// JAX threefry2x32-20 (KAT-verified vs Random123)
__device__ __forceinline__ void threefry2x32(unsigned k0, unsigned k1,
                                             unsigned &x0, unsigned &x1) {
  unsigned k2 = k0 ^ k1 ^ 0x1BD11BDAu;
  x0 += k0; x1 += k1;
#define TFR(d) { x0 += x1; x1 = __funnelshift_l(x1, x1, (d)); x1 ^= x0; }
  TFR(13) TFR(15) TFR(26) TFR(6)
  x0 += k1; x1 += k2 + 1u;
  TFR(17) TFR(29) TFR(16) TFR(24)
  x0 += k2; x1 += k0 + 2u;
  TFR(13) TFR(15) TFR(26) TFR(6)
  x0 += k0; x1 += k1 + 3u;
  TFR(17) TFR(29) TFR(16) TFR(24)
  x0 += k1; x1 += k2 + 4u;
  TFR(13) TFR(15) TFR(26) TFR(6)
  x0 += k2; x1 += k0 + 5u;
#undef TFR
}

// XLA ErfInv32 (Giles), exact coefficients
__device__ __forceinline__ float erfinv_xla(float x) {
  float w = -log1pf(-x * x);
  float p;
  if (w < 5.0f) {
    w -= 2.5f;
    p = 2.81022636e-08f;
    p = fmaf(p, w, 3.43273939e-07f);
    p = fmaf(p, w, -3.5233877e-06f);
    p = fmaf(p, w, -4.39150654e-06f);
    p = fmaf(p, w, 0.00021858087f);
    p = fmaf(p, w, -0.00125372503f);
    p = fmaf(p, w, -0.00417768164f);
    p = fmaf(p, w, 0.246640727f);
    p = fmaf(p, w, 1.50140941f);
  } else {
    w = sqrtf(w) - 3.0f;
    p = -0.000200214257f;
    p = fmaf(p, w, 0.000100950558f);
    p = fmaf(p, w, 0.00134934322f);
    p = fmaf(p, w, -0.00367342844f);
    p = fmaf(p, w, 0.00573950773f);
    p = fmaf(p, w, -0.0076224613f);
    p = fmaf(p, w, 0.00943887047f);
    p = fmaf(p, w, 1.00167406f);
    p = fmaf(p, w, 2.83297682f);
  }
  return p * x;
}

__device__ __forceinline__ unsigned enc_params(const int* p, int b, int stride) {
  unsigned n = (unsigned)p[(3*b + 0) * stride];
  unsigned k = (unsigned)p[(3*b + 1) * stride];
  unsigned m = (unsigned)p[(3*b + 2) * stride];
  return (n << 20) | ((k & 1023u) << 10) | (m & 1023u);
}

// np.unique(params, axis=0, return_inverse) replication + positions/keys
__global__ void prep_kernel(const int* __restrict__ params, int B, int stride) {
  const int T = 256;
  int tid = threadIdx.x;
  __shared__ unsigned enc[MAXC];
  __shared__ unsigned senc[MAXC];
  __shared__ int nc_s;
  __shared__ unsigned short cnt[256][MAXC];
  if (tid < MAXC) enc[tid] = 0xFFFFFFFFu;
#pragma unroll
  for (int j = 0; j < MAXC; j++) cnt[tid][j] = 0;
  if (tid == 0) nc_s = 0;
  __syncthreads();

  int chunk = (B + T - 1) / T;
  int b0 = tid * chunk;
  int b1 = min(B, b0 + chunk);

  for (int b = b0; b < b1; b++) {
    unsigned e = enc_params(params, b, stride);
    for (int j = 0; j < MAXC; j++) {
      unsigned cur = enc[j];
      if (cur == e) break;
      if (cur == 0xFFFFFFFFu) {
        unsigned old = atomicCAS(&enc[j], 0xFFFFFFFFu, e);
        if (old == 0xFFFFFFFFu || old == e) break;
      }
    }
  }
  __syncthreads();

  if (tid == 0) {
    int nc = 0;
    while (nc < MAXC && enc[nc] != 0xFFFFFFFFu) nc++;
    for (int i = 0; i < nc; i++) {
      int bi = i; unsigned best = enc[i];
      for (int j = i + 1; j < nc; j++) if (enc[j] < best) { best = enc[j]; bi = j; }
      unsigned t = enc[i]; enc[i] = enc[bi]; enc[bi] = t;
    }
    for (int i = 0; i < nc; i++) senc[i] = enc[i];
    nc_s = nc;
  }
  __syncthreads();
  int nc = nc_s;

  for (int b = b0; b < b1; b++) {
    unsigned e = enc_params(params, b, stride);
    int g = 0;
    for (int j = 0; j < nc; j++) if (senc[j] == e) { g = j; break; }
    cnt[tid][g]++;
  }
  __syncthreads();

  if (tid < MAXC) {
    int run = 0;
    for (int c = 0; c < T; c++) {
      int t = cnt[c][tid];
      cnt[c][tid] = (unsigned short)run;
      run += t;
    }
    d_gsz[tid] = run;
  }
  __syncthreads();

  for (int b = b0; b < b1; b++) {
    unsigned e = enc_params(params, b, stride);
    int g = 0;
    for (int j = 0; j < nc; j++) if (senc[j] == e) { g = j; break; }
    d_gid[b] = g;
    d_pos[b] = cnt[tid][g]++;
  }

  if (tid < MAXC) {
    if (tid < nc) {
      unsigned e = senc[tid];
      int n = (int)(e >> 20), k = (int)((e >> 10) & 1023u), m = (int)(e & 1023u);
      d_cn[tid] = n; d_ck[tid] = k; d_cm[tid] = m;
      unsigned x0 = 0u, x1 = (unsigned)tid;      // fold_in(key(42), i): ctr (0,i)
      threefry2x32(0u, 42u, x0, x1);
      d_key0[tid] = x0; d_key1[tid] = x1;
      int gsz = d_gsz[tid];
      d_val[tid] = (m + 1 <= n) && (k > 0) && (n - k >= 0) && (gsz > 0) &&
                   (k <= KMAXC) && (n - k <= PW) && (m <= 4) ? 1 : 0;
    } else {
      d_val[tid] = 0;
    }
  }
}

// one CTA per batch element
__global__ void __launch_bounds__(TMAIN, 1)
main_kernel(const float* __restrict__ P_padded,
            const float* __restrict__ y_pred, int B) {
  int b = blockIdx.x;
  int tid = threadIdx.x;
  if (b >= B) return;
  int gid = d_gid[b];
  if (!d_val[gid]) { if (tid == 0) d_pen[b] = 0.0f; return; }

  int k = d_ck[gid], m = d_cm[gid];
  int nk = d_cn[gid] - k; if (nk > PW) nk = PW;
  unsigned key0 = d_key0[gid], key1 = d_key1[gid];
  unsigned base = (unsigned)d_pos[b] * (unsigned)(NS * k);

  extern __shared__ float smem[];
  float* Xs = smem;            // NS * k   (exact fp32 — needed for |X| top-k)
  float* Ps = smem + NS * k;   // k * PW   (TF32-rounded einsum operand)

  // exact JAX normals: PARTITIONABLE threefry (jax>=0.4.30 default).
  // Per element with flat index ge: cipher counter (hi=0, lo=ge); 32-bit
  // output = out0 ^ out1.
  int EX = NS * k;
  for (int e = tid; e < EX; e += TMAIN) {
    unsigned ge = base + (unsigned)e;
    unsigned x0 = 0u, x1 = ge;
    threefry2x32(key0, key1, x0, x1);
    unsigned bits = x0 ^ x1;
    float f = __uint_as_float((bits >> 9) | 0x3F800000u) - 1.0f;  // [0,1)
    float u = fmaf(f, 2.0f, -0.99999994f);   // (hi-lo) rounds to 2.0f
    u = fmaxf(-0.99999994f, u);
    Xs[e] = 1.41421356f * erfinv_xla(u);
  }

  // stage P[b,:k,:nk] TF32-rounded, zero-pad columns to PW
  const float* Pb = P_padded + (size_t)b * (size_t)(KMAXC * PW);
  for (int i = tid; i < k * PW; i += TMAIN) {
    int row = i >> 7, col = i & (PW - 1);
    Ps[i] = (col < nk) ? tf32_rne(Pb[row * PW + col]) : 0.0f;
  }
  __syncthreads();

  int lane = tid & 31;
  int warp = tid >> 5;                 // 16 warps * 8 rows = 128 rows
  const float4* P4 = (const float4*)Ps;
  int k4 = k >> 2;
  bool kd4 = ((k & 3) == 0);
  float wmax_hm = 0.0f;

  for (int t = 0; t < 2; t++) {
    int s0 = (warp * 2 + t) * 4;
    float acc[4][4];
#pragma unroll
    for (int r = 0; r < 4; r++)
#pragma unroll
      for (int q = 0; q < 4; q++) acc[r][q] = 0.0f;

    const float* X0 = Xs + (s0 + 0) * k;
    const float* X1 = Xs + (s0 + 1) * k;
    const float* X2 = Xs + (s0 + 2) * k;
    const float* X3 = Xs + (s0 + 3) * k;

    if (kd4) {
      const float4* X40 = (const float4*)X0;
      const float4* X41 = (const float4*)X1;
      const float4* X42 = (const float4*)X2;
      const float4* X43 = (const float4*)X3;
      for (int kk = 0; kk < k4; kk++) {
        float4 p0 = P4[(kk * 4 + 0) * 32 + lane];
        float4 p1 = P4[(kk * 4 + 1) * 32 + lane];
        float4 p2 = P4[(kk * 4 + 2) * 32 + lane];
        float4 p3 = P4[(kk * 4 + 3) * 32 + lane];
        float4 xv;
#define DOROW(r, XP)                                                            \
        xv = tf32_rne4(XP[kk]);                                                 \
        acc[r][0]=fmaf(xv.x,p0.x,acc[r][0]); acc[r][1]=fmaf(xv.x,p0.y,acc[r][1]); \
        acc[r][2]=fmaf(xv.x,p0.z,acc[r][2]); acc[r][3]=fmaf(xv.x,p0.w,acc[r][3]); \
        acc[r][0]=fmaf(xv.y,p1.x,acc[r][0]); acc[r][1]=fmaf(xv.y,p1.y,acc[r][1]); \
        acc[r][2]=fmaf(xv.y,p1.z,acc[r][2]); acc[r][3]=fmaf(xv.y,p1.w,acc[r][3]); \
        acc[r][0]=fmaf(xv.z,p2.x,acc[r][0]); acc[r][1]=fmaf(xv.z,p2.y,acc[r][1]); \
        acc[r][2]=fmaf(xv.z,p2.z,acc[r][2]); acc[r][3]=fmaf(xv.z,p2.w,acc[r][3]); \
        acc[r][0]=fmaf(xv.w,p3.x,acc[r][0]); acc[r][1]=fmaf(xv.w,p3.y,acc[r][1]); \
        acc[r][2]=fmaf(xv.w,p3.z,acc[r][2]); acc[r][3]=fmaf(xv.w,p3.w,acc[r][3]);
        DOROW(0, X40) DOROW(1, X41) DOROW(2, X42) DOROW(3, X43)
#undef DOROW
      }
    } else {
      for (int kk = 0; kk < k; kk++) {
        float4 p0 = P4[kk * 32 + lane];
        float xv;
        xv = tf32_rne(X0[kk]);
        acc[0][0]=fmaf(xv,p0.x,acc[0][0]); acc[0][1]=fmaf(xv,p0.y,acc[0][1]);
        acc[0][2]=fmaf(xv,p0.z,acc[0][2]); acc[0][3]=fmaf(xv,p0.w,acc[0][3]);
        xv = tf32_rne(X1[kk]);
        acc[1][0]=fmaf(xv,p0.x,acc[1][0]); acc[1][1]=fmaf(xv,p0.y,acc[1][1]);
        acc[1][2]=fmaf(xv,p0.z,acc[1][2]); acc[1][3]=fmaf(xv,p0.w,acc[1][3]);
        xv = tf32_rne(X2[kk]);
        acc[2][0]=fmaf(xv,p0.x,acc[2][0]); acc[2][1]=fmaf(xv,p0.y,acc[2][1]);
        acc[2][2]=fmaf(xv,p0.z,acc[2][2]); acc[2][3]=fmaf(xv,p0.w,acc[2][3]);
        xv = tf32_rne(X3[kk]);
        acc[3][0]=fmaf(xv,p0.x,acc[3][0]); acc[3][1]=fmaf(xv,p0.y,acc[3][1]);
        acc[3][2]=fmaf(xv,p0.z,acc[3][2]); acc[3][3]=fmaf(xv,p0.w,acc[3][3]);
      }
    }

    // fused top-5 of |[X_row, (X@P)_row]| per sample row
#pragma unroll
    for (int r = 0; r < 4; r++) {
      float t0 = 0.f, t1 = 0.f, t2 = 0.f, t3 = 0.f, t4 = 0.f;
#define INS(vv) { float _v=(vv), _m;                          \
      _m=fmaxf(t0,_v); _v=fminf(t0,_v); t0=_m;                \
      _m=fmaxf(t1,_v); _v=fminf(t1,_v); t1=_m;                \
      _m=fmaxf(t2,_v); _v=fminf(t2,_v); t2=_m;                \
      _m=fmaxf(t3,_v); _v=fminf(t3,_v); t3=_m;                \
      t4=fmaxf(t4,_v); }
      INS(fabsf(acc[r][0])) INS(fabsf(acc[r][1]))
      INS(fabsf(acc[r][2])) INS(fabsf(acc[r][3]))
      const float* Xr = Xs + (s0 + r) * k;
      if (kd4) {
        if (lane * 4 < k) {
          float4 v = ((const float4*)Xr)[lane];
          INS(fabsf(v.x)) INS(fabsf(v.y)) INS(fabsf(v.z)) INS(fabsf(v.w))
        }
      } else {
        int kb = lane * 4;
        if (kb     < k) INS(fabsf(Xr[kb]))
        if (kb + 1 < k) INS(fabsf(Xr[kb + 1]))
        if (kb + 2 < k) INS(fabsf(Xr[kb + 2]))
        if (kb + 3 < k) INS(fabsf(Xr[kb + 3]))
      }
#undef INS
      // warp tournament: extract global top-5 (nonneg float order == uint order)
      float e0 = t0, e1 = t1, e2 = t2, e3 = t3, e4 = t4;
      float g0 = 0.f, gm = 0.f;
#pragma unroll
      for (int j = 0; j < 5; j++) {
        unsigned hb = __float_as_uint(e0);
        unsigned mx = __reduce_max_sync(FULLMASK, hb);
        float val = __uint_as_float(mx);
        if (j == 0) g0 = val;
        if (j == m) gm = val;
        unsigned ball = __ballot_sync(FULLMASK, hb == mx);
        if (lane == (__ffs(ball) - 1)) { e0 = e1; e1 = e2; e2 = e3; e3 = e4; e4 = 0.f; }
      }
      wmax_hm = fmaxf(wmax_hm, g0 / (gm + 1e-9f));
    }
  }

  __shared__ float swm[TMAIN / 32];
  if (lane == 0) swm[warp] = wmax_hm;
  __syncthreads();
  if (tid == 0) {
    float mx = swm[0];
#pragma unroll
    for (int i = 1; i < TMAIN / 32; i++) mx = fmaxf(mx, swm[i]);
    d_pen[b] = fmaxf(mx - y_pred[b], 0.0f);
  }
}

__global__ void final_kernel(const float* __restrict__ y_pred,
                             const float* __restrict__ y_true,
                             int B, float* __restrict__ out) {
  __shared__ float s1[512], s2[512];
  int tid = threadIdx.x;
  float a = 0.f, v = 0.f;
  for (int b = tid; b < B; b += 512) {
    float lp = log2f(fmaxf(y_pred[b], 1e-9f));
    float lt = log2f(fmaxf(y_true[b], 1e-9f));
    float d = lt - lp;
    a += d * d;
    v += d_pen[b];
  }
  s1[tid] = a; s2[tid] = v;
  __syncthreads();
  for (int s = 256; s > 0; s >>= 1) {
    if (tid < s) { s1[tid] += s1[tid + s]; s2[tid] += s2[tid + s]; }
    __syncthreads();
  }
  if (tid == 0) {
    float logmse = s1[0] / (float)B;
    float viol   = s2[0] / (float)B;
    out[0] = logmse + 0.5f * viol;
    out[1] = logmse;
    out[2] = viol;
  }
}

extern "C" void kernel_launch(void* const* d_in, const int* in_sizes, int n_in,
                              void* d_out, int out_size) {
  const float* y_pred   = (const float*)d_in[0];
  const float* y_true   = (const float*)d_in[1];
  const float* P_padded = (const float*)d_in[2];
  const int*   params   = (const int*)d_in[3];
  float* out = (float*)d_out;
  int B = in_sizes[0];
  // params may arrive as int64 (element count doubles when viewed as int32)
  int stride = (in_sizes[3] >= B * 3 * 2) ? 2 : 1;

  int smem_bytes = (NS * KMAXC + KMAXC * PW) * (int)sizeof(float);  // 128 KB
  cudaFuncSetAttribute(main_kernel,
                       cudaFuncAttributeMaxDynamicSharedMemorySize, smem_bytes);

  prep_kernel<<<1, 256>>>(params, B, stride);
  main_kernel<<<B, TMAIN, smem_bytes>>>(P_padded, y_pred, B);
  final_kernel<<<1, 512>>>(y_pred, y_true, B, out);
  (void)n_in; (void)out_size;
}

// round 5
// speedup vs baseline: 1.1550x; 1.1550x over previous
#include <cuda_runtime.h>
#include <cstdint>

#define FULLMASK 0xFFFFFFFFu
#define MAXC  16
#define BMAX  4096
#define NS    128
#define KMAXC 128
#define PW    128
#define TMAIN 512

#define FMA2(d, a, b, c) \
  asm("fma.rn.f32x2 %0, %1, %2, %3;" : "=l"(d) : "l"(a), "l"(b), "l"(c))
#define UNPACK2(lo, hi, v) \
  asm("mov.b64 {%0, %1}, %2;" : "=f"(lo), "=f"(hi) : "l"(v))

__device__ int      d_gid[BMAX];
__device__ int      d_pos[BMAX];
__device__ int      d_cn[MAXC];
__device__ int      d_ck[MAXC];
__device__ int      d_cm[MAXC];
__device__ unsigned d_key0[MAXC];
__device__ unsigned d_key1[MAXC];
__device__ int      d_gsz[MAXC];
__device__ int      d_val[MAXC];
__device__ float    d_pen[BMAX];

// TF32 round-to-nearest-even (13 low mantissa bits dropped).
__device__ __forceinline__ float tf32_rne(float x) {
  unsigned u = __float_as_uint(x);
  u = (u + 0xFFFu + ((u >> 13) & 1u)) & 0xFFFFE000u;
  return __uint_as_float(u);
}

// JAX threefry2x32-20 (KAT-verified vs Random123)
__device__ __forceinline__ void threefry2x32(unsigned k0, unsigned k1,
                                             unsigned &x0, unsigned &x1) {
  unsigned k2 = k0 ^ k1 ^ 0x1BD11BDAu;
  x0 += k0; x1 += k1;
#define TFR(d) { x0 += x1; x1 = __funnelshift_l(x1, x1, (d)); x1 ^= x0; }
  TFR(13) TFR(15) TFR(26) TFR(6)
  x0 += k1; x1 += k2 + 1u;
  TFR(17) TFR(29) TFR(16) TFR(24)
  x0 += k2; x1 += k0 + 2u;
  TFR(13) TFR(15) TFR(26) TFR(6)
  x0 += k0; x1 += k1 + 3u;
  TFR(17) TFR(29) TFR(16) TFR(24)
  x0 += k1; x1 += k2 + 4u;
  TFR(13) TFR(15) TFR(26) TFR(6)
  x0 += k2; x1 += k0 + 5u;
#undef TFR
}

// XLA ErfInv32 (Giles), exact coefficients
__device__ __forceinline__ float erfinv_xla(float x) {
  float w = -log1pf(-x * x);
  float p;
  if (w < 5.0f) {
    w -= 2.5f;
    p = 2.81022636e-08f;
    p = fmaf(p, w, 3.43273939e-07f);
    p = fmaf(p, w, -3.5233877e-06f);
    p = fmaf(p, w, -4.39150654e-06f);
    p = fmaf(p, w, 0.00021858087f);
    p = fmaf(p, w, -0.00125372503f);
    p = fmaf(p, w, -0.00417768164f);
    p = fmaf(p, w, 0.246640727f);
    p = fmaf(p, w, 1.50140941f);
  } else {
    w = sqrtf(w) - 3.0f;
    p = -0.000200214257f;
    p = fmaf(p, w, 0.000100950558f);
    p = fmaf(p, w, 0.00134934322f);
    p = fmaf(p, w, -0.00367342844f);
    p = fmaf(p, w, 0.00573950773f);
    p = fmaf(p, w, -0.0076224613f);
    p = fmaf(p, w, 0.00943887047f);
    p = fmaf(p, w, 1.00167406f);
    p = fmaf(p, w, 2.83297682f);
  }
  return p * x;
}

__device__ __forceinline__ unsigned enc_params(const int* p, int b, int stride) {
  unsigned n = (unsigned)p[(3*b + 0) * stride];
  unsigned k = (unsigned)p[(3*b + 1) * stride];
  unsigned m = (unsigned)p[(3*b + 2) * stride];
  return (n << 20) | ((k & 1023u) << 10) | (m & 1023u);
}

// np.unique(params, axis=0, return_inverse) replication + positions/keys
__global__ void prep_kernel(const int* __restrict__ params, int B, int stride) {
  const int T = 256;
  int tid = threadIdx.x;
  __shared__ unsigned enc[MAXC];
  __shared__ unsigned senc[MAXC];
  __shared__ int nc_s;
  __shared__ unsigned short cnt[256][MAXC];
  if (tid < MAXC) enc[tid] = 0xFFFFFFFFu;
#pragma unroll
  for (int j = 0; j < MAXC; j++) cnt[tid][j] = 0;
  if (tid == 0) nc_s = 0;
  __syncthreads();

  int chunk = (B + T - 1) / T;
  int b0 = tid * chunk;
  int b1 = min(B, b0 + chunk);

  for (int b = b0; b < b1; b++) {
    unsigned e = enc_params(params, b, stride);
    for (int j = 0; j < MAXC; j++) {
      unsigned cur = enc[j];
      if (cur == e) break;
      if (cur == 0xFFFFFFFFu) {
        unsigned old = atomicCAS(&enc[j], 0xFFFFFFFFu, e);
        if (old == 0xFFFFFFFFu || old == e) break;
      }
    }
  }
  __syncthreads();

  if (tid == 0) {
    int nc = 0;
    while (nc < MAXC && enc[nc] != 0xFFFFFFFFu) nc++;
    for (int i = 0; i < nc; i++) {
      int bi = i; unsigned best = enc[i];
      for (int j = i + 1; j < nc; j++) if (enc[j] < best) { best = enc[j]; bi = j; }
      unsigned t = enc[i]; enc[i] = enc[bi]; enc[bi] = t;
    }
    for (int i = 0; i < nc; i++) senc[i] = enc[i];
    nc_s = nc;
  }
  __syncthreads();
  int nc = nc_s;

  for (int b = b0; b < b1; b++) {
    unsigned e = enc_params(params, b, stride);
    int g = 0;
    for (int j = 0; j < nc; j++) if (senc[j] == e) { g = j; break; }
    cnt[tid][g]++;
  }
  __syncthreads();

  if (tid < MAXC) {
    int run = 0;
    for (int c = 0; c < T; c++) {
      int t = cnt[c][tid];
      cnt[c][tid] = (unsigned short)run;
      run += t;
    }
    d_gsz[tid] = run;
  }
  __syncthreads();

  for (int b = b0; b < b1; b++) {
    unsigned e = enc_params(params, b, stride);
    int g = 0;
    for (int j = 0; j < nc; j++) if (senc[j] == e) { g = j; break; }
    d_gid[b] = g;
    d_pos[b] = cnt[tid][g]++;
  }

  if (tid < MAXC) {
    if (tid < nc) {
      unsigned e = senc[tid];
      int n = (int)(e >> 20), k = (int)((e >> 10) & 1023u), m = (int)(e & 1023u);
      d_cn[tid] = n; d_ck[tid] = k; d_cm[tid] = m;
      unsigned x0 = 0u, x1 = (unsigned)tid;      // fold_in(key(42), i): ctr (0,i)
      threefry2x32(0u, 42u, x0, x1);
      d_key0[tid] = x0; d_key1[tid] = x1;
      int gsz = d_gsz[tid];
      d_val[tid] = (m + 1 <= n) && (k > 0) && (n - k >= 0) && (gsz > 0) &&
                   (k <= KMAXC) && (n - k <= PW) && (m <= 4) ? 1 : 0;
    } else {
      d_val[tid] = 0;
    }
  }
}

// one CTA per batch element
__global__ void __launch_bounds__(TMAIN, 1)
main_kernel(const float* __restrict__ P_padded,
            const float* __restrict__ y_pred, int B) {
  int b = blockIdx.x;
  int tid = threadIdx.x;
  if (b >= B) return;
  int gid = d_gid[b];
  if (!d_val[gid]) { if (tid == 0) d_pen[b] = 0.0f; return; }

  int k = d_ck[gid], m = d_cm[gid];
  int nk = d_cn[gid] - k; if (nk > PW) nk = PW;
  unsigned key0 = d_key0[gid], key1 = d_key1[gid];
  unsigned base = (unsigned)d_pos[b] * (unsigned)(NS * k);

  extern __shared__ float smem[];
  float2* Xd = (float2*)smem;            // NS*k duplicated pairs (x,x) — 8B each
  float*  Ps = smem + NS * k * 2;        // k * PW (TF32-rounded)

  // exact JAX normals: partitionable threefry (counter (0, ge); out = x0^x1),
  // stored DUPLICATED so the packed GEMM multiplier is a single LDS.64 bcast.
  int EX = NS * k;
  for (int e = tid; e < EX; e += TMAIN) {
    unsigned ge = base + (unsigned)e;
    unsigned x0 = 0u, x1 = ge;
    threefry2x32(key0, key1, x0, x1);
    unsigned bits = x0 ^ x1;
    float f = __uint_as_float((bits >> 9) | 0x3F800000u) - 1.0f;  // [0,1)
    float u = fmaf(f, 2.0f, -0.99999994f);
    u = fmaxf(-0.99999994f, u);
    float xval = 1.41421356f * erfinv_xla(u);
    Xd[e] = make_float2(xval, xval);
  }

  // stage P[b,:k,:nk] TF32-rounded, zero-pad columns to PW
  const float* Pb = P_padded + (size_t)b * (size_t)(KMAXC * PW);
  for (int i = tid; i < k * PW; i += TMAIN) {
    int row = i >> 7, col = i & (PW - 1);
    Ps[i] = (col < nk) ? tf32_rne(Pb[row * PW + col]) : 0.0f;
  }
  __syncthreads();

  int lane = tid & 31;
  int warp = tid >> 5;                 // 16 warps * 8 rows = 128 rows
  const unsigned long long* Xu = (const unsigned long long*)Xd;
  float wmax_hm = 0.0f;

  for (int t = 0; t < 2; t++) {
    int s0 = (warp * 2 + t) * 4;
    unsigned long long a01[4], a23[4];
#pragma unroll
    for (int r = 0; r < 4; r++) { a01[r] = 0ull; a23[r] = 0ull; }

    const unsigned long long* X0 = Xu + (s0 + 0) * k;
    const unsigned long long* X1 = Xu + (s0 + 1) * k;
    const unsigned long long* X2 = Xu + (s0 + 2) * k;
    const unsigned long long* X3 = Xu + (s0 + 3) * k;
    const float* Pl = Ps + lane * 4;

#pragma unroll 4
    for (int kk = 0; kk < k; kk++) {
      ulonglong2 pv = *(const ulonglong2*)(Pl + kk * PW);
      unsigned long long xx;
      xx = X0[kk]; FMA2(a01[0], xx, pv.x, a01[0]); FMA2(a23[0], xx, pv.y, a23[0]);
      xx = X1[kk]; FMA2(a01[1], xx, pv.x, a01[1]); FMA2(a23[1], xx, pv.y, a23[1]);
      xx = X2[kk]; FMA2(a01[2], xx, pv.x, a01[2]); FMA2(a23[2], xx, pv.y, a23[2]);
      xx = X3[kk]; FMA2(a01[3], xx, pv.x, a01[3]); FMA2(a23[3], xx, pv.y, a23[3]);
    }

    // fused top-5 of |[X_row, (X@P)_row]| per sample row
#pragma unroll
    for (int r = 0; r < 4; r++) {
      float c0, c1, c2, c3;
      UNPACK2(c0, c1, a01[r]);
      UNPACK2(c2, c3, a23[r]);
      float t0 = 0.f, t1 = 0.f, t2 = 0.f, t3 = 0.f, t4 = 0.f;
#define INS(vv) { float _v=(vv), _m;                          \
      _m=fmaxf(t0,_v); _v=fminf(t0,_v); t0=_m;                \
      _m=fmaxf(t1,_v); _v=fminf(t1,_v); t1=_m;                \
      _m=fmaxf(t2,_v); _v=fminf(t2,_v); t2=_m;                \
      _m=fmaxf(t3,_v); _v=fminf(t3,_v); t3=_m;                \
      t4=fmaxf(t4,_v); }
      INS(fabsf(c0)) INS(fabsf(c1)) INS(fabsf(c2)) INS(fabsf(c3))
      {
        const float2* Xr = Xd + (s0 + r) * k;
        int kb = lane * 4;
        if (kb     < k) INS(fabsf(Xr[kb].x))
        if (kb + 1 < k) INS(fabsf(Xr[kb + 1].x))
        if (kb + 2 < k) INS(fabsf(Xr[kb + 2].x))
        if (kb + 3 < k) INS(fabsf(Xr[kb + 3].x))
      }
#undef INS
      // warp tournament: extract global top-5 (nonneg float order == uint order)
      float e0 = t0, e1 = t1, e2 = t2, e3 = t3, e4 = t4;
      float g0 = 0.f, gm = 0.f;
#pragma unroll
      for (int j = 0; j < 5; j++) {
        unsigned hb = __float_as_uint(e0);
        unsigned mx = __reduce_max_sync(FULLMASK, hb);
        float val = __uint_as_float(mx);
        if (j == 0) g0 = val;
        if (j == m) gm = val;
        unsigned ball = __ballot_sync(FULLMASK, hb == mx);
        if (lane == (__ffs(ball) - 1)) { e0 = e1; e1 = e2; e2 = e3; e3 = e4; e4 = 0.f; }
      }
      wmax_hm = fmaxf(wmax_hm, g0 / (gm + 1e-9f));
    }
  }

  __shared__ float swm[TMAIN / 32];
  if (lane == 0) swm[warp] = wmax_hm;
  __syncthreads();
  if (tid == 0) {
    float mx = swm[0];
#pragma unroll
    for (int i = 1; i < TMAIN / 32; i++) mx = fmaxf(mx, swm[i]);
    d_pen[b] = fmaxf(mx - y_pred[b], 0.0f);
  }
}

__global__ void final_kernel(const float* __restrict__ y_pred,
                             const float* __restrict__ y_true,
                             int B, float* __restrict__ out) {
  __shared__ float s1[512], s2[512];
  int tid = threadIdx.x;
  float a = 0.f, v = 0.f;
  for (int b = tid; b < B; b += 512) {
    float lp = log2f(fmaxf(y_pred[b], 1e-9f));
    float lt = log2f(fmaxf(y_true[b], 1e-9f));
    float d = lt - lp;
    a += d * d;
    v += d_pen[b];
  }
  s1[tid] = a; s2[tid] = v;
  __syncthreads();
  for (int s = 256; s > 0; s >>= 1) {
    if (tid < s) { s1[tid] += s1[tid + s]; s2[tid] += s2[tid + s]; }
    __syncthreads();
  }
  if (tid == 0) {
    float logmse = s1[0] / (float)B;
    float viol   = s2[0] / (float)B;
    out[0] = logmse + 0.5f * viol;
    out[1] = logmse;
    out[2] = viol;
  }
}

extern "C" void kernel_launch(void* const* d_in, const int* in_sizes, int n_in,
                              void* d_out, int out_size) {
  const float* y_pred   = (const float*)d_in[0];
  const float* y_true   = (const float*)d_in[1];
  const float* P_padded = (const float*)d_in[2];
  const int*   params   = (const int*)d_in[3];
  float* out = (float*)d_out;
  int B = in_sizes[0];
  // params may arrive as int64 (element count doubles when viewed as int32)
  int stride = (in_sizes[3] >= B * 3 * 2) ? 2 : 1;

  // Xd (duplicated, 8B/elem) + Ps: 128*128*8 + 128*128*4 = 192 KB
  int smem_bytes = (NS * KMAXC * 2 + KMAXC * PW) * (int)sizeof(float);
  cudaFuncSetAttribute(main_kernel,
                       cudaFuncAttributeMaxDynamicSharedMemorySize, smem_bytes);

  prep_kernel<<<1, 256>>>(params, B, stride);
  main_kernel<<<B, TMAIN, smem_bytes>>>(P_padded, y_pred, B);
  final_kernel<<<1, 512>>>(y_pred, y_true, B, out);
  (void)n_in; (void)out_size;
}

// round 6
// speedup vs baseline: 1.5097x; 1.3071x over previous
#include <cuda_runtime.h>
#include <cstdint>

#define FULLMASK 0xFFFFFFFFu
#define MAXC  16
#define BMAX  4096
#define NS    128
#define HROWS 64
#define KMAXC 128
#define PW    128

#define FMA2(d, a, b, c) \
  asm("fma.rn.f32x2 %0, %1, %2, %3;" : "=l"(d) : "l"(a), "l"(b), "l"(c))
#define UNPACK2(lo, hi, v) \
  asm("mov.b64 {%0, %1}, %2;" : "=f"(lo), "=f"(hi) : "l"(v))
#define PACK_DUP(d, s) \
  asm("mov.b64 %0, {%1, %1};" : "=l"(d) : "f"(s))

__device__ int      d_gid[BMAX];
__device__ int      d_pos[BMAX];
__device__ int      d_cn[MAXC];
__device__ int      d_ck[MAXC];
__device__ int      d_cm[MAXC];
__device__ unsigned d_key0[MAXC];
__device__ unsigned d_key1[MAXC];
__device__ int      d_gsz[MAXC];
__device__ int      d_val[MAXC];
__device__ unsigned d_hm[BMAX];   // max_hm per batch elem, float bits (nonneg)

// TF32 round-to-nearest-even (13 low mantissa bits dropped).
__device__ __forceinline__ float tf32_rne(float x) {
  unsigned u = __float_as_uint(x);
  u = (u + 0xFFFu + ((u >> 13) & 1u)) & 0xFFFFE000u;
  return __uint_as_float(u);
}

// JAX threefry2x32-20 (KAT-verified vs Random123)
__device__ __forceinline__ void threefry2x32(unsigned k0, unsigned k1,
                                             unsigned &x0, unsigned &x1) {
  unsigned k2 = k0 ^ k1 ^ 0x1BD11BDAu;
  x0 += k0; x1 += k1;
#define TFR(d) { x0 += x1; x1 = __funnelshift_l(x1, x1, (d)); x1 ^= x0; }
  TFR(13) TFR(15) TFR(26) TFR(6)
  x0 += k1; x1 += k2 + 1u;
  TFR(17) TFR(29) TFR(16) TFR(24)
  x0 += k2; x1 += k0 + 2u;
  TFR(13) TFR(15) TFR(26) TFR(6)
  x0 += k0; x1 += k1 + 3u;
  TFR(17) TFR(29) TFR(16) TFR(24)
  x0 += k1; x1 += k2 + 4u;
  TFR(13) TFR(15) TFR(26) TFR(6)
  x0 += k2; x1 += k0 + 5u;
#undef TFR
}

// XLA ErfInv32 (Giles), exact coefficients
__device__ __forceinline__ float erfinv_xla(float x) {
  float w = -log1pf(-x * x);
  float p;
  if (w < 5.0f) {
    w -= 2.5f;
    p = 2.81022636e-08f;
    p = fmaf(p, w, 3.43273939e-07f);
    p = fmaf(p, w, -3.5233877e-06f);
    p = fmaf(p, w, -4.39150654e-06f);
    p = fmaf(p, w, 0.00021858087f);
    p = fmaf(p, w, -0.00125372503f);
    p = fmaf(p, w, -0.00417768164f);
    p = fmaf(p, w, 0.246640727f);
    p = fmaf(p, w, 1.50140941f);
  } else {
    w = sqrtf(w) - 3.0f;
    p = -0.000200214257f;
    p = fmaf(p, w, 0.000100950558f);
    p = fmaf(p, w, 0.00134934322f);
    p = fmaf(p, w, -0.00367342844f);
    p = fmaf(p, w, 0.00573950773f);
    p = fmaf(p, w, -0.0076224613f);
    p = fmaf(p, w, 0.00943887047f);
    p = fmaf(p, w, 1.00167406f);
    p = fmaf(p, w, 2.83297682f);
  }
  return p * x;
}

__device__ __forceinline__ unsigned enc_params(const int* p, int b, int stride) {
  unsigned n = (unsigned)p[(3*b + 0) * stride];
  unsigned k = (unsigned)p[(3*b + 1) * stride];
  unsigned m = (unsigned)p[(3*b + 2) * stride];
  return (n << 20) | ((k & 1023u) << 10) | (m & 1023u);
}

// np.unique(params, axis=0, return_inverse) replication + positions/keys
__global__ void prep_kernel(const int* __restrict__ params, int B, int stride) {
  const int T = 256;
  int tid = threadIdx.x;
  __shared__ unsigned enc[MAXC];
  __shared__ unsigned senc[MAXC];
  __shared__ int nc_s;
  __shared__ unsigned short cnt[256][MAXC];
  if (tid < MAXC) enc[tid] = 0xFFFFFFFFu;
#pragma unroll
  for (int j = 0; j < MAXC; j++) cnt[tid][j] = 0;
  if (tid == 0) nc_s = 0;
  for (int i = tid; i < B; i += T) d_hm[i] = 0u;   // zero hm accumulators
  __syncthreads();

  int chunk = (B + T - 1) / T;
  int b0 = tid * chunk;
  int b1 = min(B, b0 + chunk);

  for (int b = b0; b < b1; b++) {
    unsigned e = enc_params(params, b, stride);
    for (int j = 0; j < MAXC; j++) {
      unsigned cur = enc[j];
      if (cur == e) break;
      if (cur == 0xFFFFFFFFu) {
        unsigned old = atomicCAS(&enc[j], 0xFFFFFFFFu, e);
        if (old == 0xFFFFFFFFu || old == e) break;
      }
    }
  }
  __syncthreads();

  if (tid == 0) {
    int nc = 0;
    while (nc < MAXC && enc[nc] != 0xFFFFFFFFu) nc++;
    for (int i = 0; i < nc; i++) {
      int bi = i; unsigned best = enc[i];
      for (int j = i + 1; j < nc; j++) if (enc[j] < best) { best = enc[j]; bi = j; }
      unsigned t = enc[i]; enc[i] = enc[bi]; enc[bi] = t;
    }
    for (int i = 0; i < nc; i++) senc[i] = enc[i];
    nc_s = nc;
  }
  __syncthreads();
  int nc = nc_s;

  for (int b = b0; b < b1; b++) {
    unsigned e = enc_params(params, b, stride);
    int g = 0;
    for (int j = 0; j < nc; j++) if (senc[j] == e) { g = j; break; }
    cnt[tid][g]++;
  }
  __syncthreads();

  if (tid < MAXC) {
    int run = 0;
    for (int c = 0; c < T; c++) {
      int t = cnt[c][tid];
      cnt[c][tid] = (unsigned short)run;
      run += t;
    }
    d_gsz[tid] = run;
  }
  __syncthreads();

  for (int b = b0; b < b1; b++) {
    unsigned e = enc_params(params, b, stride);
    int g = 0;
    for (int j = 0; j < nc; j++) if (senc[j] == e) { g = j; break; }
    d_gid[b] = g;
    d_pos[b] = cnt[tid][g]++;
  }

  if (tid < MAXC) {
    if (tid < nc) {
      unsigned e = senc[tid];
      int n = (int)(e >> 20), k = (int)((e >> 10) & 1023u), m = (int)(e & 1023u);
      d_cn[tid] = n; d_ck[tid] = k; d_cm[tid] = m;
      unsigned x0 = 0u, x1 = (unsigned)tid;      // fold_in(key(42), i): ctr (0,i)
      threefry2x32(0u, 42u, x0, x1);
      d_key0[tid] = x0; d_key1[tid] = x1;
      int gsz = d_gsz[tid];
      d_val[tid] = (m + 1 <= n) && (k > 0) && (n - k >= 0) && (gsz > 0) &&
                   (k <= KMAXC) && (n - k <= PW) && (m <= 4) ? 1 : 0;
    } else {
      d_val[tid] = 0;
    }
  }
}

// two CTAs per batch element (64 sample rows each); 256 threads, 8 warps.
// smem = 64*128*4 (X) + 128*128*4 (P) = 96 KB -> 2 CTAs/SM, so one CTA's
// alu-bound X-gen overlaps the co-resident CTA's fma-bound GEMM.
__global__ void __launch_bounds__(256, 2)
main_kernel(const float* __restrict__ P_padded, int B) {
  int b = blockIdx.x >> 1;
  int h = blockIdx.x & 1;
  int tid = threadIdx.x;
  if (b >= B) return;
  int gid = d_gid[b];
  if (!d_val[gid]) return;           // d_hm stays 0 -> penalty 0

  int k = d_ck[gid], m = d_cm[gid];
  int nk = d_cn[gid] - k; if (nk > PW) nk = PW;
  unsigned key0 = d_key0[gid], key1 = d_key1[gid];
  unsigned base = (unsigned)d_pos[b] * (unsigned)(NS * k)
                + (unsigned)(h * HROWS * k);

  extern __shared__ float smem[];
  float* Xs = smem;                    // HROWS * k (<= 32 KB)
  float* Ps = smem + HROWS * KMAXC;    // k * PW (TF32-rounded, zero-padded)

  // exact JAX normals: partitionable threefry (counter (0, ge); out = x0^x1)
  int EX = HROWS * k;
  for (int e = tid; e < EX; e += 256) {
    unsigned ge = base + (unsigned)e;
    unsigned x0 = 0u, x1 = ge;
    threefry2x32(key0, key1, x0, x1);
    unsigned bits = x0 ^ x1;
    float f = __uint_as_float((bits >> 9) | 0x3F800000u) - 1.0f;  // [0,1)
    float u = fmaf(f, 2.0f, -0.99999994f);
    u = fmaxf(-0.99999994f, u);
    Xs[e] = 1.41421356f * erfinv_xla(u);
  }

  // stage P[b,:k,:nk] TF32-rounded (vectorized), zero-pad columns to PW
  {
    const float4* Pb4 = (const float4*)(P_padded + (size_t)b * (KMAXC * PW));
    float4* Ps4 = (float4*)Ps;
    int EP4 = (k * PW) >> 2;
    for (int i = tid; i < EP4; i += 256) {
      int col = (i & (PW / 4 - 1)) * 4;
      float4 v = Pb4[i];
      v.x = (col + 0 < nk) ? tf32_rne(v.x) : 0.0f;
      v.y = (col + 1 < nk) ? tf32_rne(v.y) : 0.0f;
      v.z = (col + 2 < nk) ? tf32_rne(v.z) : 0.0f;
      v.w = (col + 3 < nk) ? tf32_rne(v.w) : 0.0f;
      Ps4[i] = v;
    }
  }
  __syncthreads();

  int lane = tid & 31;
  int warp = tid >> 5;                // 8 warps * 8 rows = 64 rows
  int r0 = warp * 8;

  unsigned long long a0[8], a1[8];
#pragma unroll
  for (int r = 0; r < 8; r++) { a0[r] = 0ull; a1[r] = 0ull; }

  const float* Pl = Ps + lane * 4;
  const float* X0 = Xs + (r0 + 0) * k;
  const float* X1 = Xs + (r0 + 1) * k;
  const float* X2 = Xs + (r0 + 2) * k;
  const float* X3 = Xs + (r0 + 3) * k;
  const float* X4 = Xs + (r0 + 4) * k;
  const float* X5 = Xs + (r0 + 5) * k;
  const float* X6 = Xs + (r0 + 6) * k;
  const float* X7 = Xs + (r0 + 7) * k;

#pragma unroll 4
  for (int kk = 0; kk < k; kk++) {
    ulonglong2 pv = *(const ulonglong2*)(Pl + kk * PW);
    unsigned long long xx;
#define ROW(r, Xp) { PACK_DUP(xx, Xp[kk]); \
    FMA2(a0[r], xx, pv.x, a0[r]); FMA2(a1[r], xx, pv.y, a1[r]); }
    ROW(0, X0) ROW(1, X1) ROW(2, X2) ROW(3, X3)
    ROW(4, X4) ROW(5, X5) ROW(6, X6) ROW(7, X7)
#undef ROW
  }

  // fused top-5 of |[X_row, (X@P)_row]| per sample row
  float wmax_hm = 0.0f;
  int kb = lane * 4;
#pragma unroll
  for (int r = 0; r < 8; r++) {
    float c0, c1, c2, c3;
    UNPACK2(c0, c1, a0[r]);
    UNPACK2(c2, c3, a1[r]);
    float t0 = 0.f, t1 = 0.f, t2 = 0.f, t3 = 0.f, t4 = 0.f;
#define INS(vv) { float _v=(vv), _m;                          \
    _m=fmaxf(t0,_v); _v=fminf(t0,_v); t0=_m;                  \
    _m=fmaxf(t1,_v); _v=fminf(t1,_v); t1=_m;                  \
    _m=fmaxf(t2,_v); _v=fminf(t2,_v); t2=_m;                  \
    _m=fmaxf(t3,_v); _v=fminf(t3,_v); t3=_m;                  \
    t4=fmaxf(t4,_v); }
    INS(fabsf(c0)) INS(fabsf(c1)) INS(fabsf(c2)) INS(fabsf(c3))
    {
      const float* Xr = Xs + (r0 + r) * k;
      if (kb     < k) INS(fabsf(Xr[kb]))
      if (kb + 1 < k) INS(fabsf(Xr[kb + 1]))
      if (kb + 2 < k) INS(fabsf(Xr[kb + 2]))
      if (kb + 3 < k) INS(fabsf(Xr[kb + 3]))
    }
#undef INS
    // warp tournament: extract global top-5 (nonneg float order == uint order)
    float e0 = t0, e1 = t1, e2 = t2, e3 = t3, e4 = t4;
    float g0 = 0.f, gm = 0.f;
#pragma unroll
    for (int j = 0; j < 5; j++) {
      unsigned hb = __float_as_uint(e0);
      unsigned mx = __reduce_max_sync(FULLMASK, hb);
      float val = __uint_as_float(mx);
      if (j == 0) g0 = val;
      if (j == m) gm = val;
      unsigned ball = __ballot_sync(FULLMASK, hb == mx);
      if (lane == (__ffs(ball) - 1)) { e0 = e1; e1 = e2; e2 = e3; e3 = e4; e4 = 0.f; }
    }
    wmax_hm = fmaxf(wmax_hm, g0 / (gm + 1e-9f));
  }

  __shared__ float swm[8];
  if (lane == 0) swm[warp] = wmax_hm;
  __syncthreads();
  if (tid == 0) {
    float mx = swm[0];
#pragma unroll
    for (int i = 1; i < 8; i++) mx = fmaxf(mx, swm[i]);
    atomicMax(&d_hm[b], __float_as_uint(mx));   // nonneg: uint order == float
  }
}

__global__ void final_kernel(const float* __restrict__ y_pred,
                             const float* __restrict__ y_true,
                             int B, float* __restrict__ out) {
  __shared__ float s1[512], s2[512];
  int tid = threadIdx.x;
  float a = 0.f, v = 0.f;
  for (int b = tid; b < B; b += 512) {
    float lp = log2f(fmaxf(y_pred[b], 1e-9f));
    float lt = log2f(fmaxf(y_true[b], 1e-9f));
    float d = lt - lp;
    a += d * d;
    v += fmaxf(__uint_as_float(d_hm[b]) - y_pred[b], 0.0f);
  }
  s1[tid] = a; s2[tid] = v;
  __syncthreads();
  for (int s = 256; s > 0; s >>= 1) {
    if (tid < s) { s1[tid] += s1[tid + s]; s2[tid] += s2[tid + s]; }
    __syncthreads();
  }
  if (tid == 0) {
    float logmse = s1[0] / (float)B;
    float viol   = s2[0] / (float)B;
    out[0] = logmse + 0.5f * viol;
    out[1] = logmse;
    out[2] = viol;
  }
}

extern "C" void kernel_launch(void* const* d_in, const int* in_sizes, int n_in,
                              void* d_out, int out_size) {
  const float* y_pred   = (const float*)d_in[0];
  const float* y_true   = (const float*)d_in[1];
  const float* P_padded = (const float*)d_in[2];
  const int*   params   = (const int*)d_in[3];
  float* out = (float*)d_out;
  int B = in_sizes[0];
  // params may arrive as int64 (element count doubles when viewed as int32)
  int stride = (in_sizes[3] >= B * 3 * 2) ? 2 : 1;

  // Xs (64*128) + Ps (128*128) floats = 96 KB -> 2 CTAs/SM
  int smem_bytes = (HROWS * KMAXC + KMAXC * PW) * (int)sizeof(float);
  cudaFuncSetAttribute(main_kernel,
                       cudaFuncAttributeMaxDynamicSharedMemorySize, smem_bytes);

  prep_kernel<<<1, 256>>>(params, B, stride);
  main_kernel<<<B * 2, 256, smem_bytes>>>(P_padded, B);
  final_kernel<<<1, 512>>>(y_pred, y_true, B, out);
  (void)n_in; (void)out_size;
}

// round 8
// speedup vs baseline: 1.9129x; 1.2670x over previous
#include <cuda_runtime.h>
#include <cstdint>

#define FULLMASK 0xFFFFFFFFu
#define MAXC  16
#define BMAX  4096
#define NS    128
#define HROWS 64
#define KMAXC 128
#define PW    128

#define XST 132   // Xs row stride (floats): A-frag loads conflict-free
#define PST 136   // Ps row stride (floats): B-frag loads conflict-free

// smem layout in floats: Xs[64*132] | Ps[128*136] | xtop[64*4*5]
#define OFF_X    0
#define OFF_P    (HROWS * XST)                    // 8448
#define OFF_XTOP (OFF_P + KMAXC * PST)            // 25856
#define SMEM_FLOATS (OFF_XTOP + HROWS * 4 * 5)    // 27136 -> 108544 B
// ctop[64 rows][8 slots][5] aliases the (dead after GEMM) Ps region
#define OFF_CTOP OFF_P

__device__ int      d_gid[BMAX];
__device__ int      d_pos[BMAX];
__device__ int      d_cn[MAXC];
__device__ int      d_ck[MAXC];
__device__ int      d_cm[MAXC];
__device__ unsigned d_key0[MAXC];
__device__ unsigned d_key1[MAXC];
__device__ int      d_gsz[MAXC];
__device__ int      d_val[MAXC];
__device__ unsigned d_hm[BMAX];   // per-b max_hm as float bits (nonneg)

// TF32 round-to-nearest-even (applied to P at staging)
__device__ __forceinline__ float tf32_rne(float x) {
  unsigned u = __float_as_uint(x);
  u = (u + 0xFFFu + ((u >> 13) & 1u)) & 0xFFFFE000u;
  return __uint_as_float(u);
}

// m16n8k8 tf32 mma (sm_80 PTX; fallback HMMA on sm_103)
__device__ __forceinline__ void mma_tf32(float* c, uint32_t a0, uint32_t a1,
                                         uint32_t a2, uint32_t a3,
                                         uint32_t b0, uint32_t b1) {
  asm volatile(
    "mma.sync.aligned.m16n8k8.row.col.f32.tf32.tf32.f32 "
    "{%0,%1,%2,%3}, {%4,%5,%6,%7}, {%8,%9}, {%0,%1,%2,%3};"
    : "+f"(c[0]), "+f"(c[1]), "+f"(c[2]), "+f"(c[3])
    : "r"(a0), "r"(a1), "r"(a2), "r"(a3), "r"(b0), "r"(b1));
}

// JAX threefry2x32-20 (KAT-verified)
__device__ __forceinline__ void threefry2x32(unsigned k0, unsigned k1,
                                             unsigned &x0, unsigned &x1) {
  unsigned k2 = k0 ^ k1 ^ 0x1BD11BDAu;
  x0 += k0; x1 += k1;
#define TFR(d) { x0 += x1; x1 = __funnelshift_l(x1, x1, (d)); x1 ^= x0; }
  TFR(13) TFR(15) TFR(26) TFR(6)
  x0 += k1; x1 += k2 + 1u;
  TFR(17) TFR(29) TFR(16) TFR(24)
  x0 += k2; x1 += k0 + 2u;
  TFR(13) TFR(15) TFR(26) TFR(6)
  x0 += k0; x1 += k1 + 3u;
  TFR(17) TFR(29) TFR(16) TFR(24)
  x0 += k1; x1 += k2 + 4u;
  TFR(13) TFR(15) TFR(26) TFR(6)
  x0 += k2; x1 += k0 + 5u;
#undef TFR
}

// XLA ErfInv32 (Giles)
__device__ __forceinline__ float erfinv_xla(float x) {
  float w = -log1pf(-x * x);
  float p;
  if (w < 5.0f) {
    w -= 2.5f;
    p = 2.81022636e-08f;
    p = fmaf(p, w, 3.43273939e-07f);
    p = fmaf(p, w, -3.5233877e-06f);
    p = fmaf(p, w, -4.39150654e-06f);
    p = fmaf(p, w, 0.00021858087f);
    p = fmaf(p, w, -0.00125372503f);
    p = fmaf(p, w, -0.00417768164f);
    p = fmaf(p, w, 0.246640727f);
    p = fmaf(p, w, 1.50140941f);
  } else {
    w = sqrtf(w) - 3.0f;
    p = -0.000200214257f;
    p = fmaf(p, w, 0.000100950558f);
    p = fmaf(p, w, 0.00134934322f);
    p = fmaf(p, w, -0.00367342844f);
    p = fmaf(p, w, 0.00573950773f);
    p = fmaf(p, w, -0.0076224613f);
    p = fmaf(p, w, 0.00943887047f);
    p = fmaf(p, w, 1.00167406f);
    p = fmaf(p, w, 2.83297682f);
  }
  return p * x;
}

__device__ __forceinline__ unsigned enc_params(const int* p, int b, int stride) {
  unsigned n = (unsigned)p[(3*b + 0) * stride];
  unsigned k = (unsigned)p[(3*b + 1) * stride];
  unsigned m = (unsigned)p[(3*b + 2) * stride];
  return (n << 20) | ((k & 1023u) << 10) | (m & 1023u);
}

// np.unique(params, axis=0, return_inverse) replication + positions/keys
__global__ void prep_kernel(const int* __restrict__ params, int B, int stride) {
  const int T = 256;
  int tid = threadIdx.x;
  __shared__ unsigned enc[MAXC];
  __shared__ unsigned senc[MAXC];
  __shared__ int nc_s;
  __shared__ unsigned short cnt[256][MAXC];
  if (tid < MAXC) enc[tid] = 0xFFFFFFFFu;
#pragma unroll
  for (int j = 0; j < MAXC; j++) cnt[tid][j] = 0;
  if (tid == 0) nc_s = 0;
  for (int i = tid; i < B; i += T) d_hm[i] = 0u;
  __syncthreads();

  int chunk = (B + T - 1) / T;
  int b0 = tid * chunk;
  int b1 = min(B, b0 + chunk);

  for (int b = b0; b < b1; b++) {
    unsigned e = enc_params(params, b, stride);
    for (int j = 0; j < MAXC; j++) {
      unsigned cur = enc[j];
      if (cur == e) break;
      if (cur == 0xFFFFFFFFu) {
        unsigned old = atomicCAS(&enc[j], 0xFFFFFFFFu, e);
        if (old == 0xFFFFFFFFu || old == e) break;
      }
    }
  }
  __syncthreads();

  if (tid == 0) {
    int nc = 0;
    while (nc < MAXC && enc[nc] != 0xFFFFFFFFu) nc++;
    for (int i = 0; i < nc; i++) {
      int bi = i; unsigned best = enc[i];
      for (int j = i + 1; j < nc; j++) if (enc[j] < best) { best = enc[j]; bi = j; }
      unsigned t = enc[i]; enc[i] = enc[bi]; enc[bi] = t;
    }
    for (int i = 0; i < nc; i++) senc[i] = enc[i];
    nc_s = nc;
  }
  __syncthreads();
  int nc = nc_s;

  for (int b = b0; b < b1; b++) {
    unsigned e = enc_params(params, b, stride);
    int g = 0;
    for (int j = 0; j < nc; j++) if (senc[j] == e) { g = j; break; }
    cnt[tid][g]++;
  }
  __syncthreads();

  if (tid < MAXC) {
    int run = 0;
    for (int c = 0; c < T; c++) {
      int t = cnt[c][tid];
      cnt[c][tid] = (unsigned short)run;
      run += t;
    }
    d_gsz[tid] = run;
  }
  __syncthreads();

  for (int b = b0; b < b1; b++) {
    unsigned e = enc_params(params, b, stride);
    int g = 0;
    for (int j = 0; j < nc; j++) if (senc[j] == e) { g = j; break; }
    d_gid[b] = g;
    d_pos[b] = cnt[tid][g]++;
  }

  if (tid < MAXC) {
    if (tid < nc) {
      unsigned e = senc[tid];
      int n = (int)(e >> 20), k = (int)((e >> 10) & 1023u), m = (int)(e & 1023u);
      d_cn[tid] = n; d_ck[tid] = k; d_cm[tid] = m;
      unsigned x0 = 0u, x1 = (unsigned)tid;      // fold_in(key(42), i)
      threefry2x32(0u, 42u, x0, x1);
      d_key0[tid] = x0; d_key1[tid] = x1;
      int gsz = d_gsz[tid];
      d_val[tid] = (m + 1 <= n) && (k > 0) && (n - k >= 0) && (gsz > 0) &&
                   (k <= KMAXC) && (n - k <= PW) && (m <= 4) ? 1 : 0;
    } else {
      d_val[tid] = 0;
    }
  }
}

#define INS(vv) { float _v=(vv), _m;                          \
  _m=fmaxf(t0,_v); _v=fminf(t0,_v); t0=_m;                    \
  _m=fmaxf(t1,_v); _v=fminf(t1,_v); t1=_m;                    \
  _m=fmaxf(t2,_v); _v=fminf(t2,_v); t2=_m;                    \
  _m=fmaxf(t3,_v); _v=fminf(t3,_v); t3=_m;                    \
  t4=fmaxf(t4,_v); }

// two CTAs per batch element (64 rows each); 256 threads; GEMM on mma.sync tf32
__global__ void __launch_bounds__(256, 2)
main_kernel(const float* __restrict__ P_padded, int B) {
  int b = blockIdx.x >> 1;
  int h = blockIdx.x & 1;
  int tid = threadIdx.x;
  if (b >= B) return;
  int gid = d_gid[b];
  if (!d_val[gid]) return;           // d_hm stays 0 -> penalty 0

  int k = d_ck[gid], m = d_cm[gid];
  int nk = d_cn[gid] - k; if (nk > PW) nk = PW;
  int k8 = (k + 7) & ~7;
  unsigned key0 = d_key0[gid], key1 = d_key1[gid];
  unsigned base = (unsigned)d_pos[b] * (unsigned)(NS * k);

  extern __shared__ float smem[];
  float* Xs   = smem + OFF_X;
  float* Ps   = smem + OFF_P;
  float* xtop = smem + OFF_XTOP;
  float* ctop = smem + OFF_CTOP;

  // ---- X generation: 4 threads per row, per-thread |X| top-5 ----
  {
    int row = tid >> 2;          // 0..63
    int q   = tid & 3;
    int kq  = k8 >> 2;
    unsigned rbase = base + (unsigned)((h * HROWS + row) * k);
    float t0 = 0.f, t1 = 0.f, t2 = 0.f, t3 = 0.f, t4 = 0.f;
    for (int j = 0; j < kq; j++) {
      int col = q * kq + j;
      float val = 0.0f;
      if (col < k) {
        unsigned x0 = 0u, x1 = rbase + (unsigned)col;   // partitionable ctr
        threefry2x32(key0, key1, x0, x1);
        unsigned bits = x0 ^ x1;
        float f = __uint_as_float((bits >> 9) | 0x3F800000u) - 1.0f;
        float u = fmaf(f, 2.0f, -0.99999994f);
        u = fmaxf(-0.99999994f, u);
        val = 1.41421356f * erfinv_xla(u);
        INS(fabsf(val))
      }
      Xs[row * XST + col] = val;
    }
    float* xt = xtop + (row * 4 + q) * 5;
    xt[0] = t0; xt[1] = t1; xt[2] = t2; xt[3] = t3; xt[4] = t4;
  }

  // ---- stage P[b,:k,:nk] TF32-rounded into padded-stride tile ----
  {
    const float4* Pb4 = (const float4*)(P_padded + (size_t)b * (KMAXC * PW));
    int tot = k8 * 32;
    for (int i = tid; i < tot; i += 256) {
      int r = i >> 5, c4 = i & 31, col = c4 * 4;
      float4 v = make_float4(0.f, 0.f, 0.f, 0.f);
      if (r < k) {
        v = Pb4[r * 32 + c4];
        v.x = (col + 0 < nk) ? tf32_rne(v.x) : 0.f;
        v.y = (col + 1 < nk) ? tf32_rne(v.y) : 0.f;
        v.z = (col + 2 < nk) ? tf32_rne(v.z) : 0.f;
        v.w = (col + 3 < nk) ? tf32_rne(v.w) : 0.f;
      }
      *(float4*)(Ps + r * PST + col) = v;
    }
  }
  __syncthreads();

  // ---- GEMM: warp = (mtile, nhalf); m16n8k8 tf32 mma.sync ----
  int lane = tid & 31;
  int warp = tid >> 5;
  int mtile = warp >> 1;           // 0..3 -> rows mtile*16..+15
  int nhalf = warp & 1;            // 0..1 -> cols nhalf*64..+63
  int r0 = mtile * 16;
  int n0 = nhalf * 64;
  int g = lane >> 2;               // groupID
  int t = lane & 3;                // threadID in group

  float acc[8][4];
#pragma unroll
  for (int nt = 0; nt < 8; nt++)
#pragma unroll
    for (int j = 0; j < 4; j++) acc[nt][j] = 0.f;

  const uint32_t* Xu = (const uint32_t*)Xs;
  const uint32_t* Pu = (const uint32_t*)Ps;
  int ksteps = k8 >> 3;
  int rA0 = (r0 + g) * XST;
  int rA1 = (r0 + g + 8) * XST;

  for (int s = 0; s < ksteps; s++) {
    int kc = s * 8;
    uint32_t a0 = Xu[rA0 + kc + t];
    uint32_t a1 = Xu[rA1 + kc + t];
    uint32_t a2 = Xu[rA0 + kc + t + 4];
    uint32_t a3 = Xu[rA1 + kc + t + 4];
    int pb0 = (kc + t) * PST + n0 + g;
    int pb1 = (kc + t + 4) * PST + n0 + g;
#pragma unroll
    for (int nt = 0; nt < 8; nt++) {
      uint32_t b0 = Pu[pb0 + nt * 8];
      uint32_t b1 = Pu[pb1 + nt * 8];
      mma_tf32(acc[nt], a0, a1, a2, a3, b0, b1);
    }
  }
  __syncthreads();   // all mma reads of Ps done; ctop may now alias Ps

  // ---- per-lane C top-5 for its two rows -> ctop[row][nhalf*4+t][5] ----
  {
    int slot = nhalf * 4 + t;
    float t0 = 0.f, t1 = 0.f, t2 = 0.f, t3 = 0.f, t4 = 0.f;
#pragma unroll
    for (int nt = 0; nt < 8; nt++) { INS(fabsf(acc[nt][0])) INS(fabsf(acc[nt][1])) }
    float* c0 = ctop + ((r0 + g) * 8 + slot) * 5;
    c0[0] = t0; c0[1] = t1; c0[2] = t2; c0[3] = t3; c0[4] = t4;
    t0 = t1 = t2 = t3 = t4 = 0.f;
#pragma unroll
    for (int nt = 0; nt < 8; nt++) { INS(fabsf(acc[nt][2])) INS(fabsf(acc[nt][3])) }
    float* c1 = ctop + ((r0 + g + 8) * 8 + slot) * 5;
    c1[0] = t0; c1[1] = t1; c1[2] = t2; c1[3] = t3; c1[4] = t4;
  }
  __syncthreads();

  // ---- merge per row (threads 0..63): 8 C-lists + 4 X-lists -> hm ----
  if (tid < 64) {
    float t0 = 0.f, t1 = 0.f, t2 = 0.f, t3 = 0.f, t4 = 0.f;
    const float* cr = ctop + tid * 8 * 5;
#pragma unroll
    for (int j = 0; j < 40; j++) INS(cr[j])
    const float* xr = xtop + tid * 4 * 5;
#pragma unroll
    for (int j = 0; j < 20; j++) INS(xr[j])
    float gm = (m <= 0) ? t0 : (m == 1) ? t1 : (m == 2) ? t2
             : (m == 3) ? t3 : t4;
    float hm = t0 / (gm + 1e-9f);
    unsigned mx = __reduce_max_sync(FULLMASK, __float_as_uint(hm));
    if (lane == 0) atomicMax(&d_hm[b], mx);   // nonneg: uint order == float
  }
}
#undef INS

__global__ void final_kernel(const float* __restrict__ y_pred,
                             const float* __restrict__ y_true,
                             int B, float* __restrict__ out) {
  __shared__ float s1[512], s2[512];
  int tid = threadIdx.x;
  float a = 0.f, v = 0.f;
  for (int b = tid; b < B; b += 512) {
    float lp = log2f(fmaxf(y_pred[b], 1e-9f));
    float lt = log2f(fmaxf(y_true[b], 1e-9f));
    float d = lt - lp;
    a += d * d;
    v += fmaxf(__uint_as_float(d_hm[b]) - y_pred[b], 0.0f);
  }
  s1[tid] = a; s2[tid] = v;
  __syncthreads();
  for (int s = 256; s > 0; s >>= 1) {
    if (tid < s) { s1[tid] += s1[tid + s]; s2[tid] += s2[tid + s]; }
    __syncthreads();
  }
  if (tid == 0) {
    float logmse = s1[0] / (float)B;
    float viol   = s2[0] / (float)B;
    out[0] = logmse + 0.5f * viol;
    out[1] = logmse;
    out[2] = viol;
  }
}

extern "C" void kernel_launch(void* const* d_in, const int* in_sizes, int n_in,
                              void* d_out, int out_size) {
  const float* y_pred   = (const float*)d_in[0];
  const float* y_true   = (const float*)d_in[1];
  const float* P_padded = (const float*)d_in[2];
  const int*   params   = (const int*)d_in[3];
  float* out = (float*)d_out;
  int B = in_sizes[0];
  int stride = (in_sizes[3] >= B * 3 * 2) ? 2 : 1;   // int64 params

  int smem_bytes = SMEM_FLOATS * (int)sizeof(float);   // 108544 B
  cudaFuncSetAttribute(main_kernel,
                       cudaFuncAttributeMaxDynamicSharedMemorySize, smem_bytes);

  prep_kernel<<<1, 256>>>(params, B, stride);
  main_kernel<<<B * 2, 256, smem_bytes>>>(P_padded, B);
  final_kernel<<<1, 512>>>(y_pred, y_true, B, out);
  (void)n_in; (void)out_size;
}

// round 9
// speedup vs baseline: 2.4637x; 1.2879x over previous
#include <cuda_runtime.h>
#include <cstdint>

#define FULLMASK 0xFFFFFFFFu
#define MAXC  16
#define BMAX  4096
#define NS    128
#define HROWS 64
#define KMAXC 128
#define PW    128

#define XST 132   // Xs row stride (floats): A-frag loads conflict-free
#define PST 136   // Ps row stride (floats): B-frag loads conflict-free

// smem layout in floats: Xs[64*132] | Pchunk[64*136] | xtop[64*4*5]
#define OFF_X    0
#define OFF_P    (HROWS * XST)                    // 8448
#define OFF_XTOP (OFF_P + HROWS * PST)            // 17152
#define SMEM_FLOATS (OFF_XTOP + HROWS * 4 * 5)    // 18432 -> 73728 B (3 CTA/SM)
// ctop[64 rows][8 slots][5] aliases the (dead after GEMM) P chunk
#define OFF_CTOP OFF_P

__device__ int      d_gid[BMAX];
__device__ int      d_pos[BMAX];
__device__ int      d_cn[MAXC];
__device__ int      d_ck[MAXC];
__device__ int      d_cm[MAXC];
__device__ unsigned d_key0[MAXC];
__device__ unsigned d_key1[MAXC];
__device__ int      d_gsz[MAXC];
__device__ int      d_val[MAXC];
__device__ unsigned d_hm[BMAX];   // per-b max_hm as float bits (nonneg)

// TF32 round-to-nearest-even (applied to P at staging)
__device__ __forceinline__ float tf32_rne(float x) {
  unsigned u = __float_as_uint(x);
  u = (u + 0xFFFu + ((u >> 13) & 1u)) & 0xFFFFE000u;
  return __uint_as_float(u);
}

// m16n8k8 tf32 mma (sm_80 PTX; fallback HMMA on sm_103)
__device__ __forceinline__ void mma_tf32(float* c, uint32_t a0, uint32_t a1,
                                         uint32_t a2, uint32_t a3,
                                         uint32_t b0, uint32_t b1) {
  asm volatile(
    "mma.sync.aligned.m16n8k8.row.col.f32.tf32.tf32.f32 "
    "{%0,%1,%2,%3}, {%4,%5,%6,%7}, {%8,%9}, {%0,%1,%2,%3};"
    : "+f"(c[0]), "+f"(c[1]), "+f"(c[2]), "+f"(c[3])
    : "r"(a0), "r"(a1), "r"(a2), "r"(a3), "r"(b0), "r"(b1));
}

// JAX threefry2x32-20 (KAT-verified)
__device__ __forceinline__ void threefry2x32(unsigned k0, unsigned k1,
                                             unsigned &x0, unsigned &x1) {
  unsigned k2 = k0 ^ k1 ^ 0x1BD11BDAu;
  x0 += k0; x1 += k1;
#define TFR(d) { x0 += x1; x1 = __funnelshift_l(x1, x1, (d)); x1 ^= x0; }
  TFR(13) TFR(15) TFR(26) TFR(6)
  x0 += k1; x1 += k2 + 1u;
  TFR(17) TFR(29) TFR(16) TFR(24)
  x0 += k2; x1 += k0 + 2u;
  TFR(13) TFR(15) TFR(26) TFR(6)
  x0 += k0; x1 += k1 + 3u;
  TFR(17) TFR(29) TFR(16) TFR(24)
  x0 += k1; x1 += k2 + 4u;
  TFR(13) TFR(15) TFR(26) TFR(6)
  x0 += k2; x1 += k0 + 5u;
#undef TFR
}

// XLA ErfInv32 (Giles). log1p(-x*x) replaced by MUFU-based log of the
// identically-rounded argument (Sterbenz-exact subtraction for x^2>=0.5);
// induced X error <= ~1e-7 rel.
__device__ __forceinline__ float erfinv_xla(float x) {
  float xx = x * x;
  float w = -__logf(1.0f - xx);
  float p;
  if (w < 5.0f) {
    w -= 2.5f;
    p = 2.81022636e-08f;
    p = fmaf(p, w, 3.43273939e-07f);
    p = fmaf(p, w, -3.5233877e-06f);
    p = fmaf(p, w, -4.39150654e-06f);
    p = fmaf(p, w, 0.00021858087f);
    p = fmaf(p, w, -0.00125372503f);
    p = fmaf(p, w, -0.00417768164f);
    p = fmaf(p, w, 0.246640727f);
    p = fmaf(p, w, 1.50140941f);
  } else {
    w = sqrtf(w) - 3.0f;
    p = -0.000200214257f;
    p = fmaf(p, w, 0.000100950558f);
    p = fmaf(p, w, 0.00134934322f);
    p = fmaf(p, w, -0.00367342844f);
    p = fmaf(p, w, 0.00573950773f);
    p = fmaf(p, w, -0.0076224613f);
    p = fmaf(p, w, 0.00943887047f);
    p = fmaf(p, w, 1.00167406f);
    p = fmaf(p, w, 2.83297682f);
  }
  return p * x;
}

__device__ __forceinline__ unsigned enc_params(const int* p, int b, int stride) {
  unsigned n = (unsigned)p[(3*b + 0) * stride];
  unsigned k = (unsigned)p[(3*b + 1) * stride];
  unsigned m = (unsigned)p[(3*b + 2) * stride];
  return (n << 20) | ((k & 1023u) << 10) | (m & 1023u);
}

// np.unique(params, axis=0, return_inverse) replication + positions/keys
__global__ void prep_kernel(const int* __restrict__ params, int B, int stride) {
  const int T = 256;
  int tid = threadIdx.x;
  __shared__ unsigned enc[MAXC];
  __shared__ unsigned senc[MAXC];
  __shared__ int nc_s;
  __shared__ unsigned short cnt[256][MAXC];
  if (tid < MAXC) enc[tid] = 0xFFFFFFFFu;
#pragma unroll
  for (int j = 0; j < MAXC; j++) cnt[tid][j] = 0;
  if (tid == 0) nc_s = 0;
  for (int i = tid; i < B; i += T) d_hm[i] = 0u;
  __syncthreads();

  int chunk = (B + T - 1) / T;
  int b0 = tid * chunk;
  int b1 = min(B, b0 + chunk);

  // set-insert with per-thread local dedup cache (8 entries)
  {
    unsigned seen[8]; int ns = 0;
    for (int b = b0; b < b1; b++) {
      unsigned e = enc_params(params, b, stride);
      bool dup = false;
#pragma unroll
      for (int i = 0; i < 8; i++) if (i < ns && seen[i] == e) dup = true;
      if (dup) continue;
      if (ns < 8) seen[ns++] = e;
      for (int j = 0; j < MAXC; j++) {
        unsigned cur = enc[j];
        if (cur == e) break;
        if (cur == 0xFFFFFFFFu) {
          unsigned old = atomicCAS(&enc[j], 0xFFFFFFFFu, e);
          if (old == 0xFFFFFFFFu || old == e) break;
        }
      }
    }
  }
  __syncthreads();

  if (tid == 0) {
    int nc = 0;
    while (nc < MAXC && enc[nc] != 0xFFFFFFFFu) nc++;
    for (int i = 0; i < nc; i++) {
      int bi = i; unsigned best = enc[i];
      for (int j = i + 1; j < nc; j++) if (enc[j] < best) { best = enc[j]; bi = j; }
      unsigned t = enc[i]; enc[i] = enc[bi]; enc[bi] = t;
    }
    for (int i = 0; i < nc; i++) senc[i] = enc[i];
    nc_s = nc;
  }
  __syncthreads();
  int nc = nc_s;

  // cache sorted encodings in registers (0xFFFFFFFF beyond nc never matches)
  unsigned se[MAXC];
#pragma unroll
  for (int j = 0; j < MAXC; j++) se[j] = (j < nc) ? senc[j] : 0xFFFFFFFFu;

  for (int b = b0; b < b1; b++) {
    unsigned e = enc_params(params, b, stride);
    int g = 0;
#pragma unroll
    for (int j = 0; j < MAXC; j++) if (se[j] == e) g = j;
    cnt[tid][g]++;
  }
  __syncthreads();

  if (tid < MAXC) {
    int run = 0;
    for (int c = 0; c < T; c++) {
      int t = cnt[c][tid];
      cnt[c][tid] = (unsigned short)run;
      run += t;
    }
    d_gsz[tid] = run;
  }
  __syncthreads();

  for (int b = b0; b < b1; b++) {
    unsigned e = enc_params(params, b, stride);
    int g = 0;
#pragma unroll
    for (int j = 0; j < MAXC; j++) if (se[j] == e) g = j;
    d_gid[b] = g;
    d_pos[b] = cnt[tid][g]++;
  }

  if (tid < MAXC) {
    if (tid < nc) {
      unsigned e = senc[tid];
      int n = (int)(e >> 20), k = (int)((e >> 10) & 1023u), m = (int)(e & 1023u);
      d_cn[tid] = n; d_ck[tid] = k; d_cm[tid] = m;
      unsigned x0 = 0u, x1 = (unsigned)tid;      // fold_in(key(42), i)
      threefry2x32(0u, 42u, x0, x1);
      d_key0[tid] = x0; d_key1[tid] = x1;
      int gsz = d_gsz[tid];
      d_val[tid] = (m + 1 <= n) && (k > 0) && (n - k >= 0) && (gsz > 0) &&
                   (k <= KMAXC) && (n - k <= PW) && (m <= 4) ? 1 : 0;
    } else {
      d_val[tid] = 0;
    }
  }
}

#define INS(vv) { float _v=(vv), _m;                          \
  _m=fmaxf(t0,_v); _v=fminf(t0,_v); t0=_m;                    \
  _m=fmaxf(t1,_v); _v=fminf(t1,_v); t1=_m;                    \
  _m=fmaxf(t2,_v); _v=fminf(t2,_v); t2=_m;                    \
  _m=fmaxf(t3,_v); _v=fminf(t3,_v); t3=_m;                    \
  t4=fmaxf(t4,_v); }

// two CTAs per batch element (64 rows each); 256 threads; mma.sync tf32 GEMM
// with P staged in two 64-k-row chunks -> 72 KB smem -> 3 CTAs/SM.
__global__ void __launch_bounds__(256, 3)
main_kernel(const float* __restrict__ P_padded, int B) {
  int b = blockIdx.x >> 1;
  int h = blockIdx.x & 1;
  int tid = threadIdx.x;
  if (b >= B) return;
  int gid = d_gid[b];
  if (!d_val[gid]) return;           // d_hm stays 0 -> penalty 0

  int k = d_ck[gid], m = d_cm[gid];
  int nk = d_cn[gid] - k; if (nk > PW) nk = PW;
  int k8 = (k + 7) & ~7;
  unsigned key0 = d_key0[gid], key1 = d_key1[gid];
  unsigned base = (unsigned)d_pos[b] * (unsigned)(NS * k);

  extern __shared__ float smem[];
  float* Xs   = smem + OFF_X;
  float* Ps   = smem + OFF_P;
  float* xtop = smem + OFF_XTOP;
  float* ctop = smem + OFF_CTOP;

  // ---- X generation: 4 threads per row, per-thread |X| top-5 ----
  {
    int row = tid >> 2;          // 0..63
    int q   = tid & 3;
    int kq  = k8 >> 2;
    unsigned rbase = base + (unsigned)((h * HROWS + row) * k);
    float t0 = 0.f, t1 = 0.f, t2 = 0.f, t3 = 0.f, t4 = 0.f;
    for (int j = 0; j < kq; j++) {
      int col = q * kq + j;
      float val = 0.0f;
      if (col < k) {
        unsigned x0 = 0u, x1 = rbase + (unsigned)col;   // partitionable ctr
        threefry2x32(key0, key1, x0, x1);
        unsigned bits = x0 ^ x1;
        float f = __uint_as_float((bits >> 9) | 0x3F800000u) - 1.0f;
        float u = fmaf(f, 2.0f, -0.99999994f);
        u = fmaxf(-0.99999994f, u);
        val = 1.41421356f * erfinv_xla(u);
        INS(fabsf(val))
      }
      Xs[row * XST + col] = val;
    }
    float* xt = xtop + (row * 4 + q) * 5;
    xt[0] = t0; xt[1] = t1; xt[2] = t2; xt[3] = t3; xt[4] = t4;
  }

  // ---- GEMM over two k-chunks of 64 rows each ----
  int lane = tid & 31;
  int warp = tid >> 5;
  int mtile = warp >> 1;           // rows mtile*16..+15
  int nhalf = warp & 1;            // cols nhalf*64..+63
  int r0 = mtile * 16;
  int n0 = nhalf * 64;
  int g = lane >> 2;
  int t = lane & 3;

  float acc[8][4];
#pragma unroll
  for (int nt = 0; nt < 8; nt++)
#pragma unroll
    for (int j = 0; j < 4; j++) acc[nt][j] = 0.f;

  const uint32_t* Xu = (const uint32_t*)Xs;
  const uint32_t* Pu = (const uint32_t*)Ps;
  const float4* Pb4 = (const float4*)(P_padded + (size_t)b * (KMAXC * PW));
  int rA0 = r0 + g;
  int rA1 = r0 + g + 8;

  for (int c = 0; c < 2; c++) {
    int kbase = c * HROWS;
    if (kbase >= k8) break;
    int rows_this = min(HROWS, k8 - kbase);
    // stage P rows [kbase, kbase+rows_this), TF32-rounded, zero-padded
    {
      int tot = rows_this * 32;
      for (int i = tid; i < tot; i += 256) {
        int r = i >> 5, c4 = i & 31, col = c4 * 4;
        int gr = kbase + r;
        float4 v = make_float4(0.f, 0.f, 0.f, 0.f);
        if (gr < k) {
          v = Pb4[gr * 32 + c4];
          v.x = (col + 0 < nk) ? tf32_rne(v.x) : 0.f;
          v.y = (col + 1 < nk) ? tf32_rne(v.y) : 0.f;
          v.z = (col + 2 < nk) ? tf32_rne(v.z) : 0.f;
          v.w = (col + 3 < nk) ? tf32_rne(v.w) : 0.f;
        }
        *(float4*)(Ps + r * PST + col) = v;
      }
    }
    __syncthreads();   // X (c==0) + P chunk ready; prior mma reads done

    int ksteps = rows_this >> 3;
    for (int s = 0; s < ksteps; s++) {
      int kc = s * 8;           // local within chunk
      int gk = kbase + kc;      // global k col for A
      uint32_t a0 = Xu[rA0 * XST + gk + t];
      uint32_t a1 = Xu[rA1 * XST + gk + t];
      uint32_t a2 = Xu[rA0 * XST + gk + t + 4];
      uint32_t a3 = Xu[rA1 * XST + gk + t + 4];
      int pb0 = (kc + t) * PST + n0 + g;
      int pb1 = (kc + t + 4) * PST + n0 + g;
#pragma unroll
      for (int nt = 0; nt < 8; nt++) {
        uint32_t b0 = Pu[pb0 + nt * 8];
        uint32_t b1 = Pu[pb1 + nt * 8];
        mma_tf32(acc[nt], a0, a1, a2, a3, b0, b1);
      }
    }
    __syncthreads();   // mma reads done before restage / ctop aliasing
  }

  // ---- per-lane C top-5 for its two rows -> ctop[row][nhalf*4+t][5] ----
  {
    int slot = nhalf * 4 + t;
    float t0 = 0.f, t1 = 0.f, t2 = 0.f, t3 = 0.f, t4 = 0.f;
#pragma unroll
    for (int nt = 0; nt < 8; nt++) { INS(fabsf(acc[nt][0])) INS(fabsf(acc[nt][1])) }
    float* c0 = ctop + ((r0 + g) * 8 + slot) * 5;
    c0[0] = t0; c0[1] = t1; c0[2] = t2; c0[3] = t3; c0[4] = t4;
    t0 = t1 = t2 = t3 = t4 = 0.f;
#pragma unroll
    for (int nt = 0; nt < 8; nt++) { INS(fabsf(acc[nt][2])) INS(fabsf(acc[nt][3])) }
    float* c1 = ctop + ((r0 + g + 8) * 8 + slot) * 5;
    c1[0] = t0; c1[1] = t1; c1[2] = t2; c1[3] = t3; c1[4] = t4;
  }
  __syncthreads();

  // ---- merge per row (threads 0..63): 8 C-lists + 4 X-lists -> hm ----
  if (tid < 64) {
    float t0 = 0.f, t1 = 0.f, t2 = 0.f, t3 = 0.f, t4 = 0.f;
    const float* cr = ctop + tid * 8 * 5;
#pragma unroll
    for (int j = 0; j < 40; j++) INS(cr[j])
    const float* xr = xtop + tid * 4 * 5;
#pragma unroll
    for (int j = 0; j < 20; j++) INS(xr[j])
    float gm = (m <= 0) ? t0 : (m == 1) ? t1 : (m == 2) ? t2
             : (m == 3) ? t3 : t4;
    float hm = t0 / (gm + 1e-9f);
    unsigned mx = __reduce_max_sync(FULLMASK, __float_as_uint(hm));
    if (lane == 0) atomicMax(&d_hm[b], mx);   // nonneg: uint order == float
  }
}
#undef INS

__global__ void final_kernel(const float* __restrict__ y_pred,
                             const float* __restrict__ y_true,
                             int B, float* __restrict__ out) {
  __shared__ float s1[512], s2[512];
  int tid = threadIdx.x;
  float a = 0.f, v = 0.f;
  for (int b = tid; b < B; b += 512) {
    float lp = log2f(fmaxf(y_pred[b], 1e-9f));
    float lt = log2f(fmaxf(y_true[b], 1e-9f));
    float d = lt - lp;
    a += d * d;
    v += fmaxf(__uint_as_float(d_hm[b]) - y_pred[b], 0.0f);
  }
  s1[tid] = a; s2[tid] = v;
  __syncthreads();
  for (int s = 256; s > 0; s >>= 1) {
    if (tid < s) { s1[tid] += s1[tid + s]; s2[tid] += s2[tid + s]; }
    __syncthreads();
  }
  if (tid == 0) {
    float logmse = s1[0] / (float)B;
    float viol   = s2[0] / (float)B;
    out[0] = logmse + 0.5f * viol;
    out[1] = logmse;
    out[2] = viol;
  }
}

extern "C" void kernel_launch(void* const* d_in, const int* in_sizes, int n_in,
                              void* d_out, int out_size) {
  const float* y_pred   = (const float*)d_in[0];
  const float* y_true   = (const float*)d_in[1];
  const float* P_padded = (const float*)d_in[2];
  const int*   params   = (const int*)d_in[3];
  float* out = (float*)d_out;
  int B = in_sizes[0];
  int stride = (in_sizes[3] >= B * 3 * 2) ? 2 : 1;   // int64 params

  int smem_bytes = SMEM_FLOATS * (int)sizeof(float);   // 73728 B
  cudaFuncSetAttribute(main_kernel,
                       cudaFuncAttributeMaxDynamicSharedMemorySize, smem_bytes);

  prep_kernel<<<1, 256>>>(params, B, stride);
  main_kernel<<<B * 2, 256, smem_bytes>>>(P_padded, B);
  final_kernel<<<1, 512>>>(y_pred, y_true, B, out);
  (void)n_in; (void)out_size;
}